// round 3
// baseline (speedup 1.0000x reference)
#include <cuda_runtime.h>
#include <cuda_bf16.h>

// Problem constants (match reference_code)
#define NPTS 8192
#define F0   8191      // N - 1 finite dim-0 pairs
#define E0   1
#define F1   4096
#define E1   8

// Output layout (flat fp32):
//   [0,     16382)  finite_dgm0  : rows (0, death)       -> float2 per row, 8B aligned
//   [16382, 16383)  essential_dgm0 : single 0
//   [16383, 24575)  finite_dgm1  : 2*F1 gathered dists   (odd base -> scalar stores)
//   [24575, 24583)  essential_dgm1 : E1 gathered dists
#define OFF_E0  (2 * F0)            // 16382
#define OFF_F1  (OFF_E0 + E0)       // 16383
#define OFF_E1  (OFF_F1 + 2 * F1)   // 24575

// Work items (one thread each):
//   [0, F0)                      : dgm0 row r -> float2 store
//   F0                           : essential_dgm0 zero
//   [F0+1, F0+1+2*F1)            : flat dim-1 pair j
//   [F0+1+2*F1, F0+1+2*F1+E1)    : essential dim-1 k
#define ITEM_F1   (F0 + 1)              // 8192
#define ITEM_E1   (ITEM_F1 + 2 * F1)    // 16384
#define N_ITEMS   (ITEM_E1 + E1)        // 16392

__device__ __forceinline__ float pair_dist(const float* __restrict__ X, int a, int b) {
    float ax = __ldg(X + 3 * a + 0);
    float ay = __ldg(X + 3 * a + 1);
    float az = __ldg(X + 3 * a + 2);
    float bx = __ldg(X + 3 * b + 0);
    float by = __ldg(X + 3 * b + 1);
    float bz = __ldg(X + 3 * b + 2);
    float dx = ax - bx, dy = ay - by, dz = az - bz;
    return sqrtf(fmaf(dx, dx, fmaf(dy, dy, dz * dz)));
}

__global__ __launch_bounds__(128, 8)
void rips_kernel(const float* __restrict__ X,
                 const int* __restrict__ idx0_finite,    // [F0,3]
                 const int* __restrict__ idx1_finite,    // [F1,4] == flat pairs [2*F1,2]
                 const int* __restrict__ idx1_essential, // [E1,2]
                 float* __restrict__ out) {
    int tid = blockIdx.x * blockDim.x + threadIdx.x;
    if (tid >= N_ITEMS) return;

    if (tid < F0) {
        // One dgm0 row: (birth=0, death=DX[idx[r,1], idx[r,2]]) as a vectorized store.
        int a = __ldg(idx0_finite + 3 * tid + 1);
        int b = __ldg(idx0_finite + 3 * tid + 2);
        float d = pair_dist(X, a, b);
        *reinterpret_cast<float2*>(out + 2 * tid) = make_float2(0.0f, d);
    } else if (tid == F0) {
        out[OFF_E0] = 0.0f;  // essential_dgm0
    } else if (tid < ITEM_E1) {
        int j = tid - ITEM_F1;                               // flat pair index [0, 2*F1)
        int2 p = __ldg(reinterpret_cast<const int2*>(idx1_finite) + j);  // 8B-aligned
        out[OFF_F1 + j] = pair_dist(X, p.x, p.y);
    } else {
        int k = tid - ITEM_E1;
        int2 p = __ldg(reinterpret_cast<const int2*>(idx1_essential) + k);
        out[OFF_E1 + k] = pair_dist(X, p.x, p.y);
    }
}

extern "C" void kernel_launch(void* const* d_in, const int* in_sizes, int n_in,
                              void* d_out, int out_size) {
    const float* X              = (const float*)d_in[0];
    const int*   idx0_finite    = (const int*)d_in[1];
    // d_in[2] = idx0_essential (unused; corresponding outputs are zeros)
    const int*   idx1_finite    = (const int*)d_in[3];
    const int*   idx1_essential = (const int*)d_in[4];
    float* out = (float*)d_out;

    const int threads = 128;
    const int blocks = (N_ITEMS + threads - 1) / threads;  // 129 -> ~1 block per SM
    rips_kernel<<<blocks, threads>>>(X, idx0_finite, idx1_finite, idx1_essential, out);
}

// round 6
// speedup vs baseline: 1.0435x; 1.0435x over previous
#include <cuda_runtime.h>
#include <cuda_bf16.h>

// Problem constants (match reference_code)
#define NPTS 8192
#define F0   8191      // N - 1 finite dim-0 pairs
#define E0   1
#define F1   4096
#define E1   8

// Output layout (flat fp32):
//   [0,     16382)  finite_dgm0   : rows (0, death)
//   [16382, 16383)  essential_dgm0: single 0
//   [16383, 24575)  finite_dgm1   : 2*F1 gathered dists
//   [24575, 24583)  essential_dgm1: E1 gathered dists
#define OFF_E0  (2 * F0)            // 16382
#define OFF_F1  (OFF_E0 + E0)       // 16383
#define OFF_E1  (OFF_F1 + 2 * F1)   // 24575

// Work items (one thread each):
//   [0, 2048)        : dgm0 quad t -> rows 4t..4t+3 (last thread: 3 rows, scalar)
//   2048             : essential_dgm0 zero
//   [2049, 6145)     : dim-1 finite ROW t (one int4 = 2 pairs) -> out[OFF_F1+2t, +1]
//   [6145, 6149)     : dim-1 essential duo t (one int4 = 2 pairs)
#define ITEM_E0D  2048
#define ITEM_F1   2049
#define ITEM_E1   (ITEM_F1 + F1)    // 6145  (F1 rows, one int4 each)
#define N_ITEMS   (ITEM_E1 + E1/2)  // 6149

__device__ __forceinline__ float pair_dist(const float* __restrict__ X, int a, int b) {
    float ax = __ldg(X + 3 * a + 0);
    float ay = __ldg(X + 3 * a + 1);
    float az = __ldg(X + 3 * a + 2);
    float bx = __ldg(X + 3 * b + 0);
    float by = __ldg(X + 3 * b + 1);
    float bz = __ldg(X + 3 * b + 2);
    float dx = ax - bx, dy = ay - by, dz = az - bz;
    return sqrtf(fmaf(dx, dx, fmaf(dy, dy, dz * dz)));
}

__global__ __launch_bounds__(128, 8)
void rips_kernel(const float* __restrict__ X,
                 const int* __restrict__ idx0_finite,    // [F0,3]
                 const int* __restrict__ idx1_finite,    // [F1,4]
                 const int* __restrict__ idx1_essential, // [E1,2]
                 float* __restrict__ out) {
    int tid = blockIdx.x * blockDim.x + threadIdx.x;
    if (tid >= N_ITEMS) return;

    if (tid < ITEM_E0D) {
        int t = tid;
        if (t < ITEM_E0D - 1) {
            // Rows 4t..4t+3: 12 index ints = 3x int4 (16B-aligned).
            const int4* p = reinterpret_cast<const int4*>(idx0_finite) + 3 * t;
            int4 w0 = __ldg(p + 0);   // [r0.v, r0.a, r0.b, r1.v]
            int4 w1 = __ldg(p + 1);   // [r1.a, r1.b, r2.v, r2.a]
            int4 w2 = __ldg(p + 2);   // [r2.b, r3.v, r3.a, r3.b]
            float d0 = pair_dist(X, w0.y, w0.z);
            float d1 = pair_dist(X, w1.x, w1.y);
            float d2 = pair_dist(X, w1.w, w2.x);
            float d3 = pair_dist(X, w2.z, w2.w);
            float4* o = reinterpret_cast<float4*>(out + 8 * t);  // 32B-aligned
            o[0] = make_float4(0.0f, d0, 0.0f, d1);
            o[1] = make_float4(0.0f, d2, 0.0f, d3);
        } else {
            // Tail: rows 8188..8190 only (row 8191 doesn't exist; avoid OOB int4).
            #pragma unroll
            for (int r = 4 * (ITEM_E0D - 1); r < F0; r++) {
                int a = __ldg(idx0_finite + 3 * r + 1);
                int b = __ldg(idx0_finite + 3 * r + 2);
                float d = pair_dist(X, a, b);
                *reinterpret_cast<float2*>(out + 2 * r) = make_float2(0.0f, d);
            }
        }
    } else if (tid == ITEM_E0D) {
        out[OFF_E0] = 0.0f;  // essential_dgm0
    } else if (tid < ITEM_E1) {
        int t = tid - ITEM_F1;  // row index [0, F1): one int4 row = 2 pairs
        int4 w = __ldg(reinterpret_cast<const int4*>(idx1_finite) + t);  // 16B-aligned
        out[OFF_F1 + 2 * t + 0] = pair_dist(X, w.x, w.y);
        out[OFF_F1 + 2 * t + 1] = pair_dist(X, w.z, w.w);
    } else {
        int t = tid - ITEM_E1;  // [0, E1/2): two essential pairs per thread
        int4 w = __ldg(reinterpret_cast<const int4*>(idx1_essential) + t);
        out[OFF_E1 + 2 * t + 0] = pair_dist(X, w.x, w.y);
        out[OFF_E1 + 2 * t + 1] = pair_dist(X, w.z, w.w);
    }
}

extern "C" void kernel_launch(void* const* d_in, const int* in_sizes, int n_in,
                              void* d_out, int out_size) {
    const float* X              = (const float*)d_in[0];
    const int*   idx0_finite    = (const int*)d_in[1];
    // d_in[2] = idx0_essential (unused; corresponding outputs are zeros)
    const int*   idx1_finite    = (const int*)d_in[3];
    const int*   idx1_essential = (const int*)d_in[4];
    float* out = (float*)d_out;

    const int threads = 128;
    const int blocks = (N_ITEMS + threads - 1) / threads;  // 49
    rips_kernel<<<blocks, threads>>>(X, idx0_finite, idx1_finite, idx1_essential, out);
}